// round 14
// baseline (speedup 1.0000x reference)
#include <cuda_runtime.h>
#include <cstdint>

#define NB 32
#define CD 64
#define TPB 256
#define ROWS 512

#define ZSTR 36                     // f32 stride of z chunk tile (32 dims + 4 pad)
#define BSTR 40                     // u32 stride of proto tables
#define SSTR 36                     // f32 stride of sims tile (alias of z tile)

// dynamic smem offsets (bytes)
#define SM_Z     0                  // 512 x 36 f32 = 73728 (aliased as sims later)
#define SM_BH    73728              // 64 x 40 u32 = 10240
#define SM_BM    83968              // 64 x 40 u32 = 10240
#define SM_RES   94208              // 512 x float4 = 8192
#define SM_HIST  102400             // 32 ints
#define SM_TOTAL 102528

__device__ __forceinline__ uint32_t smem_u32(const void* p) {
    uint32_t a;
    asm("{ .reg .u64 t; cvta.to.shared.u64 t, %1; cvt.u32.u64 %0, t; }" : "=r"(a) : "l"(p));
    return a;
}
__device__ __forceinline__ uint32_t f2tf(float x) {
    uint32_t r;
    asm("cvt.rna.tf32.f32 %0, %1;" : "=r"(r) : "f"(x));
    return r;
}
__device__ __forceinline__ void mma_tf32(float* c,
                                         uint32_t a0, uint32_t a1, uint32_t a2, uint32_t a3,
                                         uint32_t b0, uint32_t b1) {
    asm volatile(
        "mma.sync.aligned.m16n8k8.row.col.f32.tf32.tf32.f32 "
        "{%0,%1,%2,%3}, {%4,%5,%6,%7}, {%8,%9}, {%0,%1,%2,%3};"
        : "+f"(c[0]), "+f"(c[1]), "+f"(c[2]), "+f"(c[3])
        : "r"(a0), "r"(a1), "r"(a2), "r"(a3), "r"(b0), "r"(b1));
}
__device__ __forceinline__ void cp_async16(uint32_t saddr, const void* gaddr, uint32_t sz) {
    asm volatile("cp.async.ca.shared.global [%0], [%1], 16, %2;"
                 :: "r"(saddr), "l"(gaddr), "r"(sz) : "memory");
}

__global__ void gc_init_util(const float* __restrict__ u_in,
                             float* __restrict__ u_out) {
    int i = threadIdx.x;
    if (i < NB) u_out[i] = u_in[i];
}

__global__ __launch_bounds__(TPB, 2)
void gc_main(const float* __restrict__ z,
             const float* __restrict__ protos,
             float* __restrict__ act,
             float* __restrict__ assign,
             float* __restrict__ util,
             int B) {
    extern __shared__ char smem[];
    float*    s_z    = (float*)(smem + SM_Z);
    uint32_t* s_bh   = (uint32_t*)(smem + SM_BH);
    uint32_t* s_bm   = (uint32_t*)(smem + SM_BM);
    float*    s_sims = (float*)(smem + SM_Z);      // alias, used after sync
    float4*   s_res  = (float4*)(smem + SM_RES);
    int*      s_hist = (int*)(smem + SM_HIST);
    const uint32_t sbase = smem_u32(smem);

    const int tid  = threadIdx.x;
    const int base = blockIdx.x * ROWS;
    const int w    = tid >> 5;
    const int lane = tid & 31;
    const int g    = lane >> 2;      // groupID
    const int c    = lane & 3;       // thread-in-group

    // ---- stage protos as tf32 h/m in [k][n] layout (conflict-free LDS.32 later)
    #pragma unroll
    for (int it = 0; it < (CD * NB) / TPB; it++) {   // 8 iters
        int idx = it * TPB + tid;
        int k = idx >> 5;
        int n = idx & 31;
        float v = protos[n * CD + k];
        uint32_t h = f2tf(v);
        uint32_t m = f2tf(v - __uint_as_float(h));
        s_bh[k * BSTR + n] = h;
        s_bm[k * BSTR + n] = m;
    }
    if (tid < NB) s_hist[tid] = 0;

    // warp owns 64 rows: 4 m16 tiles
    float acc[4][4][4];
    #pragma unroll
    for (int t = 0; t < 4; t++)
        #pragma unroll
        for (int nt = 0; nt < 4; nt++)
            #pragma unroll
            for (int j = 0; j < 4; j++) acc[t][nt][j] = 0.0f;

    const int rb = w * 64;

    for (int ch = 0; ch < 2; ch++) {
        if (ch) __syncthreads();      // protect s_z overwrite
        // ---- stage 32-dim z chunk via cp.async (zero-fill OOB rows)
        #pragma unroll
        for (int it = 0; it < (ROWS * 8) / TPB; it++) {   // 16 iters
            int idx = it * TPB + tid;
            int row = idx >> 3;
            int d4  = idx & 7;
            int grow = base + row;
            const float* gp = z + (size_t)(grow < B ? grow : 0) * CD + ch * 32 + 4 * d4;
            uint32_t sz = (grow < B) ? 16u : 0u;
            cp_async16(sbase + SM_Z + (uint32_t)(row * ZSTR + 4 * d4) * 4, gp, sz);
        }
        asm volatile("cp.async.commit_group;");
        asm volatile("cp.async.wait_group 0;" ::: "memory");
        __syncthreads();

        // ---- 4 k-steps per chunk
        #pragma unroll
        for (int kk = 0; kk < 4; kk++) {
            const int krl = 8 * kk + c;          // local dim in chunk
            const int krg = ch * 32 + krl;       // global dim (B table index)

            // B high fragments (conflict-free LDS.32: banks 8c+g distinct)
            uint32_t bh0[4], bh1[4];
            #pragma unroll
            for (int nt = 0; nt < 4; nt++) {
                const int n = nt * 8 + g;
                bh0[nt] = s_bh[krg * BSTR + n];
                bh1[nt] = s_bh[(krg + 4) * BSTR + n];
            }

            // A fragments: fp32 load + tf32 high part (round-to-nearest)
            float    x[4][4];
            uint32_t ah[4][4];
            #pragma unroll
            for (int t = 0; t < 4; t++) {
                const int r = rb + t * 16 + g;
                x[t][0] = s_z[r * ZSTR + krl];
                x[t][1] = s_z[(r + 8) * ZSTR + krl];
                x[t][2] = s_z[r * ZSTR + krl + 4];
                x[t][3] = s_z[(r + 8) * ZSTR + krl + 4];
                #pragma unroll
                for (int j = 0; j < 4; j++) ah[t][j] = f2tf(x[t][j]);
            }

            // hh
            #pragma unroll
            for (int t = 0; t < 4; t++)
                #pragma unroll
                for (int nt = 0; nt < 4; nt++)
                    mma_tf32(acc[t][nt], ah[t][0], ah[t][1], ah[t][2], ah[t][3],
                             bh0[nt], bh1[nt]);

            // B mid fragments
            uint32_t bm0[4], bm1[4];
            #pragma unroll
            for (int nt = 0; nt < 4; nt++) {
                const int n = nt * 8 + g;
                bm0[nt] = s_bm[krg * BSTR + n];
                bm1[nt] = s_bm[(krg + 4) * BSTR + n];
            }

            // hm
            #pragma unroll
            for (int t = 0; t < 4; t++)
                #pragma unroll
                for (int nt = 0; nt < 4; nt++)
                    mma_tf32(acc[t][nt], ah[t][0], ah[t][1], ah[t][2], ah[t][3],
                             bm0[nt], bm1[nt]);

            // A mid = raw fp32 residual bits (tf32 operand read truncates low bits;
            // extra error <= 2^-22 |x|, below current noise floor)
            uint32_t am[4][4];
            #pragma unroll
            for (int t = 0; t < 4; t++)
                #pragma unroll
                for (int j = 0; j < 4; j++)
                    am[t][j] = __float_as_uint(x[t][j] - __uint_as_float(ah[t][j]));

            // mh
            #pragma unroll
            for (int t = 0; t < 4; t++)
                #pragma unroll
                for (int nt = 0; nt < 4; nt++)
                    mma_tf32(acc[t][nt], am[t][0], am[t][1], am[t][2], am[t][3],
                             bh0[nt], bh1[nt]);
        }
    }
    __syncthreads();   // all z reads done; alias region as sims

    // ---- scatter C fragments to sims tile [row][32] (stride 36)
    #pragma unroll
    for (int t = 0; t < 4; t++) {
        const int r = rb + t * 16 + g;
        #pragma unroll
        for (int nt = 0; nt < 4; nt++) {
            const int col = nt * 8 + 2 * c;
            *(float2*)&s_sims[r * SSTR + col]       = make_float2(acc[t][nt][0], acc[t][nt][1]);
            *(float2*)&s_sims[(r + 8) * SSTR + col] = make_float2(acc[t][nt][2], acc[t][nt][3]);
        }
    }
    __syncthreads();

    // ---- per-row epilogue: 2 rows per thread: top-3 + softmax (exact, stable ties)
    #pragma unroll
    for (int rr = 0; rr < 2; rr++) {
        const int rl   = rr * TPB + tid;
        const int grow = base + rl;
        float v[32];
        #pragma unroll
        for (int j = 0; j < 8; j++) {
            float4 q = *(float4*)&s_sims[rl * SSTR + 4 * j];
            v[4 * j] = q.x; v[4 * j + 1] = q.y; v[4 * j + 2] = q.z; v[4 * j + 3] = q.w;
        }
        float v0 = -2.0f, v1 = -2.0f, v2 = -2.0f;
        int   i0 = 0,     i1 = 0,     i2 = 0;
        #pragma unroll
        for (int n = 0; n < NB; n++) {
            const float x = v[n];
            if (x > v2) {
                if (x > v1) {
                    if (x > v0) { v2 = v1; i2 = i1; v1 = v0; i1 = i0; v0 = x; i0 = n; }
                    else        { v2 = v1; i2 = i1; v1 = x;  i1 = n; }
                } else          { v2 = x;  i2 = n; }
            }
        }
        if (grow < B) {
            const float e1  = __expf((v1 - v0) * 0.2f);
            const float e2  = __expf((v2 - v0) * 0.2f);
            const float inv = 1.0f / (1.0f + e1 + e2);
            s_res[rl] = make_float4(inv, e1 * inv, e2 * inv,
                                    __int_as_float(i0 | (i1 << 8) | (i2 << 16)));
            assign[grow] = (float)i0;
            atomicAdd(&s_hist[i0], 1);
        }
    }
    __syncthreads();

    // ---- coalesced act stores: one 128B STG per row (each warp its 64 rows)
    #pragma unroll 4
    for (int rr = 0; rr < 64; rr++) {
        const int rl   = w * 64 + rr;
        const int grow = base + rl;
        if (grow < B) {
            const float4 res = s_res[rl];
            const int pk = __float_as_int(res.w);
            const int i0 = pk & 255, i1 = (pk >> 8) & 255, i2 = (pk >> 16) & 255;
            float val = 0.0f;
            if (lane == i0) val = res.x;
            if (lane == i1) val = res.y;
            if (lane == i2) val = res.z;
            act[(size_t)grow * NB + lane] = val;
        }
    }

    if (tid < NB) {
        const int cnt = s_hist[tid];
        if (cnt) atomicAdd(&util[tid], (float)cnt);
    }
}

extern "C" void kernel_launch(void* const* d_in, const int* in_sizes, int n_in,
                              void* d_out, int out_size) {
    const float* z      = (const float*)d_in[0];
    const float* protos = (const float*)d_in[1];
    const float* u_in   = (const float*)d_in[2];

    const int B = in_sizes[0] / CD;

    float* out    = (float*)d_out;
    float* act    = out;
    float* assign = out + (size_t)B * NB;
    float* util   = out + (size_t)B * (NB + 1);

    cudaFuncSetAttribute(gc_main, cudaFuncAttributeMaxDynamicSharedMemorySize, SM_TOTAL);

    gc_init_util<<<1, 32>>>(u_in, util);

    const int grid = (B + ROWS - 1) / ROWS;
    gc_main<<<grid, TPB, SM_TOTAL>>>(z, protos, act, assign, util, B);
}

// round 15
// speedup vs baseline: 1.1142x; 1.1142x over previous
#include <cuda_runtime.h>
#include <cstdint>

#define NB 32
#define CD 64
#define TPB 256
#define ROWS 256

#define ZSTR 20                     // f32 stride of 16-dim z chunk rows (16 data + 4 pad)
#define BSTR 40                     // u32 stride of proto tables
#define SSTR 36                     // f32 stride of sims tile (alias of z buffers)
#define ZBUF (ROWS * ZSTR)          // floats per buffer (5120)

// dynamic smem offsets (bytes)
#define SM_Z     0                  // 2 buffers x 20480 = 40960 (aliased as sims later)
#define SM_BH    40960              // 64 x 40 u32 = 10240
#define SM_BM    51200              // 64 x 40 u32 = 10240
#define SM_RES   61440              // 256 x float4 = 4096
#define SM_HIST  65536              // 32 ints
#define SM_TOTAL 65664

__device__ __forceinline__ uint32_t smem_u32(const void* p) {
    uint32_t a;
    asm("{ .reg .u64 t; cvta.to.shared.u64 t, %1; cvt.u32.u64 %0, t; }" : "=r"(a) : "l"(p));
    return a;
}
__device__ __forceinline__ uint32_t f2tf(float x) {
    uint32_t r;
    asm("cvt.rna.tf32.f32 %0, %1;" : "=r"(r) : "f"(x));
    return r;
}
__device__ __forceinline__ void mma_tf32(float* c,
                                         uint32_t a0, uint32_t a1, uint32_t a2, uint32_t a3,
                                         uint32_t b0, uint32_t b1) {
    asm volatile(
        "mma.sync.aligned.m16n8k8.row.col.f32.tf32.tf32.f32 "
        "{%0,%1,%2,%3}, {%4,%5,%6,%7}, {%8,%9}, {%0,%1,%2,%3};"
        : "+f"(c[0]), "+f"(c[1]), "+f"(c[2]), "+f"(c[3])
        : "r"(a0), "r"(a1), "r"(a2), "r"(a3), "r"(b0), "r"(b1));
}
__device__ __forceinline__ void cp_async16(uint32_t saddr, const void* gaddr, uint32_t sz) {
    asm volatile("cp.async.ca.shared.global [%0], [%1], 16, %2;"
                 :: "r"(saddr), "l"(gaddr), "r"(sz) : "memory");
}
template <int N>
__device__ __forceinline__ void cp_wait() {
    asm volatile("cp.async.wait_group %0;" :: "n"(N) : "memory");
}

__global__ void gc_init_util(const float* __restrict__ u_in,
                             float* __restrict__ u_out) {
    int i = threadIdx.x;
    if (i < NB) u_out[i] = u_in[i];
}

__global__ __launch_bounds__(TPB, 3)
void gc_main(const float* __restrict__ z,
             const float* __restrict__ protos,
             float* __restrict__ act,
             float* __restrict__ assign,
             float* __restrict__ util,
             int B) {
    extern __shared__ char smem[];
    float*    s_z    = (float*)(smem + SM_Z);
    uint32_t* s_bh   = (uint32_t*)(smem + SM_BH);
    uint32_t* s_bm   = (uint32_t*)(smem + SM_BM);
    float*    s_sims = (float*)(smem + SM_Z);      // alias, used after mainloop
    float4*   s_res  = (float4*)(smem + SM_RES);
    int*      s_hist = (int*)(smem + SM_HIST);
    const uint32_t sbase = smem_u32(smem);

    const int tid  = threadIdx.x;
    const int base = blockIdx.x * ROWS;
    const int w    = tid >> 5;
    const int lane = tid & 31;
    const int g    = lane >> 2;      // groupID
    const int c    = lane & 3;       // thread-in-group

    // ---- stage chunk ch (16 dims) into buffer b via cp.async
    auto stage = [&](int ch, int b) {
        #pragma unroll
        for (int it = 0; it < (ROWS * 4) / TPB; it++) {   // 4 iters
            int idx = it * TPB + tid;
            int row = idx >> 2;
            int d4  = idx & 3;
            int grow = base + row;
            const float* gp = z + (size_t)(grow < B ? grow : 0) * CD + ch * 16 + 4 * d4;
            uint32_t sz = (grow < B) ? 16u : 0u;
            cp_async16(sbase + SM_Z + (uint32_t)(b * ZBUF + row * ZSTR + 4 * d4) * 4, gp, sz);
        }
        asm volatile("cp.async.commit_group;");
    };

    // ---- prologue: chunks 0,1 in flight
    stage(0, 0);
    stage(1, 1);

    // ---- stage protos as tf32 h/m in [k][n] layout (overlaps with cp.async)
    #pragma unroll
    for (int it = 0; it < (CD * NB) / TPB; it++) {   // 8 iters
        int idx = it * TPB + tid;
        int k = idx >> 5;
        int n = idx & 31;
        float v = protos[n * CD + k];
        uint32_t h = f2tf(v);
        uint32_t m = f2tf(v - __uint_as_float(h));
        s_bh[k * BSTR + n] = h;
        s_bm[k * BSTR + n] = m;
    }
    if (tid < NB) s_hist[tid] = 0;

    float acc[2][4][4];
    #pragma unroll
    for (int t = 0; t < 2; t++)
        #pragma unroll
        for (int nt = 0; nt < 4; nt++)
            #pragma unroll
            for (int j = 0; j < 4; j++) acc[t][nt][j] = 0.0f;

    const int rb = w * 32;

    #pragma unroll
    for (int ch = 0; ch < 4; ch++) {
        // wait for chunk ch (allow the in-flight successor to keep going)
        if (ch < 3) cp_wait<1>(); else cp_wait<0>();
        __syncthreads();

        const float* zb = s_z + (ch & 1) * ZBUF;

        // ---- 2 k-steps per 16-dim chunk
        #pragma unroll
        for (int kk = 0; kk < 2; kk++) {
            const int krl = 8 * kk + c;          // dim within chunk
            const int krg = ch * 16 + krl;       // global dim (B table index)

            // B high fragments (conflict-free LDS.32)
            uint32_t bh0[4], bh1[4];
            #pragma unroll
            for (int nt = 0; nt < 4; nt++) {
                const int n = nt * 8 + g;
                bh0[nt] = s_bh[krg * BSTR + n];
                bh1[nt] = s_bh[(krg + 4) * BSTR + n];
            }

            // A fragments: fp32 load + tf32 high part
            float    x[2][4];
            uint32_t ah[2][4];
            #pragma unroll
            for (int t = 0; t < 2; t++) {
                const int r = rb + t * 16 + g;
                x[t][0] = zb[r * ZSTR + krl];
                x[t][1] = zb[(r + 8) * ZSTR + krl];
                x[t][2] = zb[r * ZSTR + krl + 4];
                x[t][3] = zb[(r + 8) * ZSTR + krl + 4];
                #pragma unroll
                for (int j = 0; j < 4; j++) ah[t][j] = f2tf(x[t][j]);
            }

            // hh
            #pragma unroll
            for (int t = 0; t < 2; t++)
                #pragma unroll
                for (int nt = 0; nt < 4; nt++)
                    mma_tf32(acc[t][nt], ah[t][0], ah[t][1], ah[t][2], ah[t][3],
                             bh0[nt], bh1[nt]);

            // B mid fragments
            uint32_t bm0[4], bm1[4];
            #pragma unroll
            for (int nt = 0; nt < 4; nt++) {
                const int n = nt * 8 + g;
                bm0[nt] = s_bm[krg * BSTR + n];
                bm1[nt] = s_bm[(krg + 4) * BSTR + n];
            }

            // hm
            #pragma unroll
            for (int t = 0; t < 2; t++)
                #pragma unroll
                for (int nt = 0; nt < 4; nt++)
                    mma_tf32(acc[t][nt], ah[t][0], ah[t][1], ah[t][2], ah[t][3],
                             bm0[nt], bm1[nt]);

            // A mid = raw fp32 residual bits (tf32 read truncates; err <= 2^-22|x|)
            uint32_t am[2][4];
            #pragma unroll
            for (int t = 0; t < 2; t++)
                #pragma unroll
                for (int j = 0; j < 4; j++)
                    am[t][j] = __float_as_uint(x[t][j] - __uint_as_float(ah[t][j]));

            // mh
            #pragma unroll
            for (int t = 0; t < 2; t++)
                #pragma unroll
                for (int nt = 0; nt < 4; nt++)
                    mma_tf32(acc[t][nt], am[t][0], am[t][1], am[t][2], am[t][3],
                             bh0[nt], bh1[nt]);
        }

        // refill this buffer with chunk ch+2
        if (ch < 2) {
            __syncthreads();          // all warps done reading buffer (ch&1)
            stage(ch + 2, ch & 1);
        }
    }
    __syncthreads();   // all z reads done; alias buffers as sims tile

    // ---- scatter C fragments to sims tile [row][32] (stride 36)
    #pragma unroll
    for (int t = 0; t < 2; t++) {
        const int r = rb + t * 16 + g;
        #pragma unroll
        for (int nt = 0; nt < 4; nt++) {
            const int col = nt * 8 + 2 * c;
            *(float2*)&s_sims[r * SSTR + col]       = make_float2(acc[t][nt][0], acc[t][nt][1]);
            *(float2*)&s_sims[(r + 8) * SSTR + col] = make_float2(acc[t][nt][2], acc[t][nt][3]);
        }
    }
    __syncthreads();

    // ---- per-thread row epilogue: top-3 + softmax (exact, stable ties)
    {
        const int grow = base + tid;
        float v[32];
        #pragma unroll
        for (int j = 0; j < 8; j++) {
            float4 q = *(float4*)&s_sims[tid * SSTR + 4 * j];
            v[4 * j] = q.x; v[4 * j + 1] = q.y; v[4 * j + 2] = q.z; v[4 * j + 3] = q.w;
        }
        float v0 = -2.0f, v1 = -2.0f, v2 = -2.0f;
        int   i0 = 0,     i1 = 0,     i2 = 0;
        #pragma unroll
        for (int n = 0; n < NB; n++) {
            const float x = v[n];
            if (x > v2) {
                if (x > v1) {
                    if (x > v0) { v2 = v1; i2 = i1; v1 = v0; i1 = i0; v0 = x; i0 = n; }
                    else        { v2 = v1; i2 = i1; v1 = x;  i1 = n; }
                } else          { v2 = x;  i2 = n; }
            }
        }
        if (grow < B) {
            const float e1  = __expf((v1 - v0) * 0.2f);
            const float e2  = __expf((v2 - v0) * 0.2f);
            const float inv = 1.0f / (1.0f + e1 + e2);
            s_res[tid] = make_float4(inv, e1 * inv, e2 * inv,
                                     __int_as_float(i0 | (i1 << 8) | (i2 << 16)));
            assign[grow] = (float)i0;
            atomicAdd(&s_hist[i0], 1);
        }
    }
    __syncthreads();

    // ---- coalesced act stores: one 128B STG per row (each warp its 32 rows)
    #pragma unroll 4
    for (int r = 0; r < 32; r++) {
        const int rl   = w * 32 + r;
        const int grow = base + rl;
        if (grow < B) {
            const float4 res = s_res[rl];
            const int pk = __float_as_int(res.w);
            const int i0 = pk & 255, i1 = (pk >> 8) & 255, i2 = (pk >> 16) & 255;
            float val = 0.0f;
            if (lane == i0) val = res.x;
            if (lane == i1) val = res.y;
            if (lane == i2) val = res.z;
            act[(size_t)grow * NB + lane] = val;
        }
    }

    if (tid < NB) {
        const int cnt = s_hist[tid];
        if (cnt) atomicAdd(&util[tid], (float)cnt);
    }
}

extern "C" void kernel_launch(void* const* d_in, const int* in_sizes, int n_in,
                              void* d_out, int out_size) {
    const float* z      = (const float*)d_in[0];
    const float* protos = (const float*)d_in[1];
    const float* u_in   = (const float*)d_in[2];

    const int B = in_sizes[0] / CD;

    float* out    = (float*)d_out;
    float* act    = out;
    float* assign = out + (size_t)B * NB;
    float* util   = out + (size_t)B * (NB + 1);

    cudaFuncSetAttribute(gc_main, cudaFuncAttributeMaxDynamicSharedMemorySize, SM_TOTAL);

    gc_init_util<<<1, 32>>>(u_in, util);

    const int grid = (B + ROWS - 1) / ROWS;
    gc_main<<<grid, TPB, SM_TOTAL>>>(z, protos, act, assign, util, B);
}

// round 16
// speedup vs baseline: 1.1754x; 1.0548x over previous
#include <cuda_runtime.h>
#include <cstdint>

#define NB 32
#define CD 64
#define TPB 256
#define ROWS 256

#define ZSTR 20                     // f32 stride of 16-dim z chunk rows (16 data + 4 pad)
#define BSTR 40                     // u32 stride of proto tables
#define SSTR 36                     // f32 stride of sims tile (aliases z + B tables)

// dynamic smem offsets (bytes)
#define SM_Z     0                  // 256 x 20 f32 = 20480
#define SM_BH    20480              // 64 x 40 u32 = 10240
#define SM_BM    30720              // 64 x 40 u32 = 10240
#define SM_RES   40960              // 256 x float4 = 4096
#define SM_HIST  45056              // 32 ints
#define SM_TOTAL 45184
// sims alias occupies [0, 36864) over z+bh+bm — all dead after mainloop

__device__ __forceinline__ uint32_t smem_u32(const void* p) {
    uint32_t a;
    asm("{ .reg .u64 t; cvta.to.shared.u64 t, %1; cvt.u32.u64 %0, t; }" : "=r"(a) : "l"(p));
    return a;
}
__device__ __forceinline__ uint32_t f2tf(float x) {
    uint32_t r;
    asm("cvt.rna.tf32.f32 %0, %1;" : "=r"(r) : "f"(x));
    return r;
}
__device__ __forceinline__ void mma_tf32(float* c,
                                         uint32_t a0, uint32_t a1, uint32_t a2, uint32_t a3,
                                         uint32_t b0, uint32_t b1) {
    asm volatile(
        "mma.sync.aligned.m16n8k8.row.col.f32.tf32.tf32.f32 "
        "{%0,%1,%2,%3}, {%4,%5,%6,%7}, {%8,%9}, {%0,%1,%2,%3};"
        : "+f"(c[0]), "+f"(c[1]), "+f"(c[2]), "+f"(c[3])
        : "r"(a0), "r"(a1), "r"(a2), "r"(a3), "r"(b0), "r"(b1));
}
__device__ __forceinline__ void cp_async16(uint32_t saddr, const void* gaddr, uint32_t sz) {
    asm volatile("cp.async.ca.shared.global [%0], [%1], 16, %2;"
                 :: "r"(saddr), "l"(gaddr), "r"(sz) : "memory");
}

__global__ void gc_init_util(const float* __restrict__ u_in,
                             float* __restrict__ u_out) {
    int i = threadIdx.x;
    if (i < NB) u_out[i] = u_in[i];
}

__global__ __launch_bounds__(TPB, 4)
void gc_main(const float* __restrict__ z,
             const float* __restrict__ protos,
             float* __restrict__ act,
             float* __restrict__ assign,
             float* __restrict__ util,
             int B) {
    extern __shared__ char smem[];
    float*    s_z    = (float*)(smem + SM_Z);
    uint32_t* s_bh   = (uint32_t*)(smem + SM_BH);
    uint32_t* s_bm   = (uint32_t*)(smem + SM_BM);
    float*    s_sims = (float*)(smem + SM_Z);      // alias, used after mainloop
    float4*   s_res  = (float4*)(smem + SM_RES);
    int*      s_hist = (int*)(smem + SM_HIST);
    const uint32_t sbase = smem_u32(smem);

    const int tid  = threadIdx.x;
    const int base = blockIdx.x * ROWS;
    const int w    = tid >> 5;
    const int lane = tid & 31;
    const int g    = lane >> 2;      // groupID
    const int c    = lane & 3;       // thread-in-group

    // ---- stage 16-dim chunk ch into the single z buffer via cp.async
    auto stage = [&](int ch) {
        #pragma unroll
        for (int it = 0; it < (ROWS * 4) / TPB; it++) {   // 4 iters
            int idx = it * TPB + tid;
            int row = idx >> 2;
            int d4  = idx & 3;
            int grow = base + row;
            const float* gp = z + (size_t)(grow < B ? grow : 0) * CD + ch * 16 + 4 * d4;
            uint32_t sz = (grow < B) ? 16u : 0u;
            cp_async16(sbase + SM_Z + (uint32_t)(row * ZSTR + 4 * d4) * 4, gp, sz);
        }
        asm volatile("cp.async.commit_group;");
    };

    stage(0);   // chunk 0 in flight; B build overlaps its latency

    // ---- stage protos as tf32 h/m in [k][n] layout; k lane-minor -> coalesced LDG
    #pragma unroll
    for (int it = 0; it < (CD * NB) / TPB; it++) {   // 8 iters
        int k = tid & 63;
        int n = it * 4 + (tid >> 6);
        float v = protos[n * CD + k];
        uint32_t h = f2tf(v);
        uint32_t m = f2tf(v - __uint_as_float(h));
        s_bh[k * BSTR + n] = h;
        s_bm[k * BSTR + n] = m;
    }
    if (tid < NB) s_hist[tid] = 0;

    float acc[2][4][4];
    #pragma unroll
    for (int t = 0; t < 2; t++)
        #pragma unroll
        for (int nt = 0; nt < 4; nt++)
            #pragma unroll
            for (int j = 0; j < 4; j++) acc[t][nt][j] = 0.0f;

    const int rb = w * 32;

    #pragma unroll
    for (int ch = 0; ch < 4; ch++) {
        asm volatile("cp.async.wait_group 0;" ::: "memory");
        __syncthreads();

        // ---- 2 k-steps per 16-dim chunk
        #pragma unroll
        for (int kk = 0; kk < 2; kk++) {
            const int krl = 8 * kk + c;          // dim within chunk
            const int krg = ch * 16 + krl;       // global dim (B table index)

            // B high fragments (conflict-free LDS.32)
            uint32_t bh0[4], bh1[4];
            #pragma unroll
            for (int nt = 0; nt < 4; nt++) {
                const int n = nt * 8 + g;
                bh0[nt] = s_bh[krg * BSTR + n];
                bh1[nt] = s_bh[(krg + 4) * BSTR + n];
            }

            // A fragments: fp32 load + tf32 high part
            float    x[2][4];
            uint32_t ah[2][4];
            #pragma unroll
            for (int t = 0; t < 2; t++) {
                const int r = rb + t * 16 + g;
                x[t][0] = s_z[r * ZSTR + krl];
                x[t][1] = s_z[(r + 8) * ZSTR + krl];
                x[t][2] = s_z[r * ZSTR + krl + 4];
                x[t][3] = s_z[(r + 8) * ZSTR + krl + 4];
                #pragma unroll
                for (int j = 0; j < 4; j++) ah[t][j] = f2tf(x[t][j]);
            }

            // hh
            #pragma unroll
            for (int t = 0; t < 2; t++)
                #pragma unroll
                for (int nt = 0; nt < 4; nt++)
                    mma_tf32(acc[t][nt], ah[t][0], ah[t][1], ah[t][2], ah[t][3],
                             bh0[nt], bh1[nt]);

            // B mid fragments
            uint32_t bm0[4], bm1[4];
            #pragma unroll
            for (int nt = 0; nt < 4; nt++) {
                const int n = nt * 8 + g;
                bm0[nt] = s_bm[krg * BSTR + n];
                bm1[nt] = s_bm[(krg + 4) * BSTR + n];
            }

            // hm
            #pragma unroll
            for (int t = 0; t < 2; t++)
                #pragma unroll
                for (int nt = 0; nt < 4; nt++)
                    mma_tf32(acc[t][nt], ah[t][0], ah[t][1], ah[t][2], ah[t][3],
                             bm0[nt], bm1[nt]);

            // A mid = raw fp32 residual bits (tf32 read truncates; err <= 2^-22|x|)
            uint32_t am[2][4];
            #pragma unroll
            for (int t = 0; t < 2; t++)
                #pragma unroll
                for (int j = 0; j < 4; j++)
                    am[t][j] = __float_as_uint(x[t][j] - __uint_as_float(ah[t][j]));

            // mh
            #pragma unroll
            for (int t = 0; t < 2; t++)
                #pragma unroll
                for (int nt = 0; nt < 4; nt++)
                    mma_tf32(acc[t][nt], am[t][0], am[t][1], am[t][2], am[t][3],
                             bh0[nt], bh1[nt]);
        }

        if (ch < 3) {
            __syncthreads();          // all warps done reading the buffer
            stage(ch + 1);
        }
    }
    __syncthreads();   // all z/B reads done; alias region as sims tile

    // ---- scatter C fragments to sims tile [row][32] (stride 36)
    #pragma unroll
    for (int t = 0; t < 2; t++) {
        const int r = rb + t * 16 + g;
        #pragma unroll
        for (int nt = 0; nt < 4; nt++) {
            const int col = nt * 8 + 2 * c;
            *(float2*)&s_sims[r * SSTR + col]       = make_float2(acc[t][nt][0], acc[t][nt][1]);
            *(float2*)&s_sims[(r + 8) * SSTR + col] = make_float2(acc[t][nt][2], acc[t][nt][3]);
        }
    }
    __syncthreads();

    // ---- per-thread row epilogue: top-3 + softmax (exact, stable ties)
    {
        const int grow = base + tid;
        float v[32];
        #pragma unroll
        for (int j = 0; j < 8; j++) {
            float4 q = *(float4*)&s_sims[tid * SSTR + 4 * j];
            v[4 * j] = q.x; v[4 * j + 1] = q.y; v[4 * j + 2] = q.z; v[4 * j + 3] = q.w;
        }
        float v0 = -2.0f, v1 = -2.0f, v2 = -2.0f;
        int   i0 = 0,     i1 = 0,     i2 = 0;
        #pragma unroll
        for (int n = 0; n < NB; n++) {
            const float x = v[n];
            if (x > v2) {
                if (x > v1) {
                    if (x > v0) { v2 = v1; i2 = i1; v1 = v0; i1 = i0; v0 = x; i0 = n; }
                    else        { v2 = v1; i2 = i1; v1 = x;  i1 = n; }
                } else          { v2 = x;  i2 = n; }
            }
        }
        if (grow < B) {
            const float e1  = __expf((v1 - v0) * 0.2f);
            const float e2  = __expf((v2 - v0) * 0.2f);
            const float inv = 1.0f / (1.0f + e1 + e2);
            s_res[tid] = make_float4(inv, e1 * inv, e2 * inv,
                                     __int_as_float(i0 | (i1 << 8) | (i2 << 16)));
            assign[grow] = (float)i0;
            atomicAdd(&s_hist[i0], 1);
        }
    }
    __syncthreads();

    // ---- coalesced act stores: one 128B STG per row (each warp its 32 rows)
    #pragma unroll 4
    for (int r = 0; r < 32; r++) {
        const int rl   = w * 32 + r;
        const int grow = base + rl;
        if (grow < B) {
            const float4 res = s_res[rl];
            const int pk = __float_as_int(res.w);
            const int i0 = pk & 255, i1 = (pk >> 8) & 255, i2 = (pk >> 16) & 255;
            float val = 0.0f;
            if (lane == i0) val = res.x;
            if (lane == i1) val = res.y;
            if (lane == i2) val = res.z;
            act[(size_t)grow * NB + lane] = val;
        }
    }

    if (tid < NB) {
        const int cnt = s_hist[tid];
        if (cnt) atomicAdd(&util[tid], (float)cnt);
    }
}

extern "C" void kernel_launch(void* const* d_in, const int* in_sizes, int n_in,
                              void* d_out, int out_size) {
    const float* z      = (const float*)d_in[0];
    const float* protos = (const float*)d_in[1];
    const float* u_in   = (const float*)d_in[2];

    const int B = in_sizes[0] / CD;

    float* out    = (float*)d_out;
    float* act    = out;
    float* assign = out + (size_t)B * NB;
    float* util   = out + (size_t)B * (NB + 1);

    cudaFuncSetAttribute(gc_main, cudaFuncAttributeMaxDynamicSharedMemorySize, SM_TOTAL);

    gc_init_util<<<1, 32>>>(u_in, util);

    const int grid = (B + ROWS - 1) / ROWS;
    gc_main<<<grid, TPB, SM_TOTAL>>>(z, protos, act, assign, util, B);
}

// round 17
// speedup vs baseline: 1.3734x; 1.1685x over previous
#include <cuda_runtime.h>
#include <cstdint>

#define NB 32
#define CD 64
#define TPB 256
#define ROWS 256

#define ZSTR 20                     // f32 stride of 16-dim z chunk rows (16 data + 4 pad)
#define BSTR 40                     // u32 stride of proto tables
#define SSTR 36                     // f32 stride of sims tile (aliases z + B tables)

// dynamic smem offsets (bytes)
#define SM_Z     0                  // 256 x 20 f32 = 20480
#define SM_BH    20480              // 64 x 40 u32 = 10240
#define SM_BM    30720              // 64 x 40 u32 = 10240
#define SM_RES   40960              // 256 x float4 = 4096
#define SM_HIST  45056              // 32 ints
#define SM_TOTAL 45184
// sims alias occupies [0, 36864) over z+bh+bm — all dead after mainloop

__device__ __forceinline__ uint32_t smem_u32(const void* p) {
    uint32_t a;
    asm("{ .reg .u64 t; cvta.to.shared.u64 t, %1; cvt.u32.u64 %0, t; }" : "=r"(a) : "l"(p));
    return a;
}
__device__ __forceinline__ uint32_t f2tf(float x) {
    uint32_t r;
    asm("cvt.rna.tf32.f32 %0, %1;" : "=r"(r) : "f"(x));
    return r;
}
__device__ __forceinline__ void mma_tf32(float* c,
                                         uint32_t a0, uint32_t a1, uint32_t a2, uint32_t a3,
                                         uint32_t b0, uint32_t b1) {
    asm volatile(
        "mma.sync.aligned.m16n8k8.row.col.f32.tf32.tf32.f32 "
        "{%0,%1,%2,%3}, {%4,%5,%6,%7}, {%8,%9}, {%0,%1,%2,%3};"
        : "+f"(c[0]), "+f"(c[1]), "+f"(c[2]), "+f"(c[3])
        : "r"(a0), "r"(a1), "r"(a2), "r"(a3), "r"(b0), "r"(b1));
}
__device__ __forceinline__ void cp_async16(uint32_t saddr, const void* gaddr, uint32_t sz) {
    asm volatile("cp.async.cg.shared.global [%0], [%1], 16, %2;"
                 :: "r"(saddr), "l"(gaddr), "r"(sz) : "memory");
}

__global__ void gc_init_util(const float* __restrict__ u_in,
                             float* __restrict__ u_out) {
    int i = threadIdx.x;
    if (i < NB) u_out[i] = u_in[i];
}

__global__ __launch_bounds__(TPB, 4)
void gc_main(const float* __restrict__ z,
             const float* __restrict__ protos,
             float* __restrict__ act,
             float* __restrict__ assign,
             float* __restrict__ util,
             int B) {
    extern __shared__ char smem[];
    float*    s_z    = (float*)(smem + SM_Z);
    uint32_t* s_bh   = (uint32_t*)(smem + SM_BH);
    uint32_t* s_bm   = (uint32_t*)(smem + SM_BM);
    float*    s_sims = (float*)(smem + SM_Z);      // alias, used after mainloop
    float4*   s_res  = (float4*)(smem + SM_RES);
    int*      s_hist = (int*)(smem + SM_HIST);
    const uint32_t sbase = smem_u32(smem);

    const int tid  = threadIdx.x;
    const int base = blockIdx.x * ROWS;
    const int w    = tid >> 5;
    const int lane = tid & 31;
    const int g    = lane >> 2;      // groupID
    const int c    = lane & 3;       // thread-in-group

    // ---- stage 16-dim chunk ch into the single z buffer via cp.async
    auto stage = [&](int ch) {
        #pragma unroll
        for (int it = 0; it < (ROWS * 4) / TPB; it++) {   // 4 iters
            int idx = it * TPB + tid;
            int row = idx >> 2;
            int d4  = idx & 3;
            int grow = base + row;
            const float* gp = z + (size_t)(grow < B ? grow : 0) * CD + ch * 16 + 4 * d4;
            uint32_t sz = (grow < B) ? 16u : 0u;
            cp_async16(sbase + SM_Z + (uint32_t)(row * ZSTR + 4 * d4) * 4, gp, sz);
        }
        asm volatile("cp.async.commit_group;");
    };

    stage(0);   // chunk 0 in flight; B build overlaps its latency

    // ---- stage protos as tf32 h/m in [k][n] layout; k lane-minor -> coalesced LDG
    #pragma unroll
    for (int it = 0; it < (CD * NB) / TPB; it++) {   // 8 iters
        int k = tid & 63;
        int n = it * 4 + (tid >> 6);
        float v = protos[n * CD + k];
        uint32_t h = f2tf(v);
        uint32_t m = f2tf(v - __uint_as_float(h));
        s_bh[k * BSTR + n] = h;
        s_bm[k * BSTR + n] = m;
    }
    if (tid < NB) s_hist[tid] = 0;

    float acc[2][4][4];
    #pragma unroll
    for (int t = 0; t < 2; t++)
        #pragma unroll
        for (int nt = 0; nt < 4; nt++)
            #pragma unroll
            for (int j = 0; j < 4; j++) acc[t][nt][j] = 0.0f;

    const int rb = w * 32;

    #pragma unroll
    for (int ch = 0; ch < 4; ch++) {
        asm volatile("cp.async.wait_group 0;" ::: "memory");
        __syncthreads();

        // ---- 2 k-steps per 16-dim chunk
        #pragma unroll
        for (int kk = 0; kk < 2; kk++) {
            const int krl = 8 * kk + c;          // dim within chunk
            const int krg = ch * 16 + krl;       // global dim (B table index)

            // B high fragments (conflict-free LDS.32)
            uint32_t bh0[4], bh1[4];
            #pragma unroll
            for (int nt = 0; nt < 4; nt++) {
                const int n = nt * 8 + g;
                bh0[nt] = s_bh[krg * BSTR + n];
                bh1[nt] = s_bh[(krg + 4) * BSTR + n];
            }

            // A fragments: fp32 load + mask-truncated tf32 high part.
            // tf32 MMA operand read uses only the top 19 bits, so
            // ah = x & 0xffffe000 is a valid high part and am = x - ah is exact.
            // Replaces the quarter-rate cvt.rna with a rate-2 LOP3.
            float    x[2][4];
            uint32_t ah[2][4];
            #pragma unroll
            for (int t = 0; t < 2; t++) {
                const int r = rb + t * 16 + g;
                x[t][0] = s_z[r * ZSTR + krl];
                x[t][1] = s_z[(r + 8) * ZSTR + krl];
                x[t][2] = s_z[r * ZSTR + krl + 4];
                x[t][3] = s_z[(r + 8) * ZSTR + krl + 4];
                #pragma unroll
                for (int j = 0; j < 4; j++)
                    ah[t][j] = __float_as_uint(x[t][j]) & 0xffffe000u;
            }

            // hh
            #pragma unroll
            for (int t = 0; t < 2; t++)
                #pragma unroll
                for (int nt = 0; nt < 4; nt++)
                    mma_tf32(acc[t][nt], ah[t][0], ah[t][1], ah[t][2], ah[t][3],
                             bh0[nt], bh1[nt]);

            // B mid fragments
            uint32_t bm0[4], bm1[4];
            #pragma unroll
            for (int nt = 0; nt < 4; nt++) {
                const int n = nt * 8 + g;
                bm0[nt] = s_bm[krg * BSTR + n];
                bm1[nt] = s_bm[(krg + 4) * BSTR + n];
            }

            // hm
            #pragma unroll
            for (int t = 0; t < 2; t++)
                #pragma unroll
                for (int nt = 0; nt < 4; nt++)
                    mma_tf32(acc[t][nt], ah[t][0], ah[t][1], ah[t][2], ah[t][3],
                             bm0[nt], bm1[nt]);

            // A mid = exact residual bits (ah has low 13 bits zero)
            uint32_t am[2][4];
            #pragma unroll
            for (int t = 0; t < 2; t++)
                #pragma unroll
                for (int j = 0; j < 4; j++)
                    am[t][j] = __float_as_uint(x[t][j] - __uint_as_float(ah[t][j]));

            // mh
            #pragma unroll
            for (int t = 0; t < 2; t++)
                #pragma unroll
                for (int nt = 0; nt < 4; nt++)
                    mma_tf32(acc[t][nt], am[t][0], am[t][1], am[t][2], am[t][3],
                             bh0[nt], bh1[nt]);
        }

        if (ch < 3) {
            __syncthreads();          // all warps done reading the buffer
            stage(ch + 1);
        }
    }
    __syncthreads();   // all z/B reads done; alias region as sims tile

    // ---- scatter C fragments to sims tile [row][32] (stride 36)
    #pragma unroll
    for (int t = 0; t < 2; t++) {
        const int r = rb + t * 16 + g;
        #pragma unroll
        for (int nt = 0; nt < 4; nt++) {
            const int col = nt * 8 + 2 * c;
            *(float2*)&s_sims[r * SSTR + col]       = make_float2(acc[t][nt][0], acc[t][nt][1]);
            *(float2*)&s_sims[(r + 8) * SSTR + col] = make_float2(acc[t][nt][2], acc[t][nt][3]);
        }
    }
    __syncthreads();

    // ---- per-thread row epilogue: top-3 + softmax (exact, stable ties)
    {
        const int grow = base + tid;
        float v[32];
        #pragma unroll
        for (int j = 0; j < 8; j++) {
            float4 q = *(float4*)&s_sims[tid * SSTR + 4 * j];
            v[4 * j] = q.x; v[4 * j + 1] = q.y; v[4 * j + 2] = q.z; v[4 * j + 3] = q.w;
        }
        float v0 = -2.0f, v1 = -2.0f, v2 = -2.0f;
        int   i0 = 0,     i1 = 0,     i2 = 0;
        #pragma unroll
        for (int n = 0; n < NB; n++) {
            const float x = v[n];
            if (x > v2) {
                if (x > v1) {
                    if (x > v0) { v2 = v1; i2 = i1; v1 = v0; i1 = i0; v0 = x; i0 = n; }
                    else        { v2 = v1; i2 = i1; v1 = x;  i1 = n; }
                } else          { v2 = x;  i2 = n; }
            }
        }
        if (grow < B) {
            const float e1  = __expf((v1 - v0) * 0.2f);
            const float e2  = __expf((v2 - v0) * 0.2f);
            const float inv = 1.0f / (1.0f + e1 + e2);
            s_res[tid] = make_float4(inv, e1 * inv, e2 * inv,
                                     __int_as_float(i0 | (i1 << 8) | (i2 << 16)));
            assign[grow] = (float)i0;
            atomicAdd(&s_hist[i0], 1);
        }
    }
    __syncthreads();

    // ---- coalesced act stores: one 128B STG per row (each warp its 32 rows)
    #pragma unroll 4
    for (int r = 0; r < 32; r++) {
        const int rl   = w * 32 + r;
        const int grow = base + rl;
        if (grow < B) {
            const float4 res = s_res[rl];
            const int pk = __float_as_int(res.w);
            const int i0 = pk & 255, i1 = (pk >> 8) & 255, i2 = (pk >> 16) & 255;
            float val = 0.0f;
            if (lane == i0) val = res.x;
            if (lane == i1) val = res.y;
            if (lane == i2) val = res.z;
            act[(size_t)grow * NB + lane] = val;
        }
    }

    if (tid < NB) {
        const int cnt = s_hist[tid];
        if (cnt) atomicAdd(&util[tid], (float)cnt);
    }
}

extern "C" void kernel_launch(void* const* d_in, const int* in_sizes, int n_in,
                              void* d_out, int out_size) {
    const float* z      = (const float*)d_in[0];
    const float* protos = (const float*)d_in[1];
    const float* u_in   = (const float*)d_in[2];

    const int B = in_sizes[0] / CD;

    float* out    = (float*)d_out;
    float* act    = out;
    float* assign = out + (size_t)B * NB;
    float* util   = out + (size_t)B * (NB + 1);

    cudaFuncSetAttribute(gc_main, cudaFuncAttributeMaxDynamicSharedMemorySize, SM_TOTAL);

    gc_init_util<<<1, 32>>>(u_in, util);

    const int grid = (B + ROWS - 1) / ROWS;
    gc_main<<<grid, TPB, SM_TOTAL>>>(z, protos, act, assign, util, B);
}